// round 13
// baseline (speedup 1.0000x reference)
#include <cuda_runtime.h>
#include <cuda_fp16.h>

#define NN 100000
#define EE 1600000
#define NB ((NN + 255) / 256)   // 391 blocks of 256

// ---------------- packed f32x2 helpers (Blackwell fma.rn.f32x2) ----------------
__device__ __forceinline__ unsigned long long dup2(float v) {
    unsigned long long d;
    unsigned int u = __float_as_uint(v);
    asm("mov.b64 %0, {%1, %2};" : "=l"(d) : "r"(u), "r"(u));
    return d;
}
__device__ __forceinline__ void ffma2(unsigned long long& d, unsigned long long a,
                                      unsigned long long b) {
    asm("fma.rn.f32x2 %0, %1, %2, %0;" : "+l"(d) : "l"(a), "l"(b));
}
__device__ __forceinline__ float2 unpack2(unsigned long long d) {
    float2 r;
    asm("mov.b64 {%0, %1}, %2;" : "=f"(r.x), "=f"(r.y) : "l"(d));
    return r;
}

// ---------------- scratch (static device globals; no runtime alloc) ----------------
__device__ __align__(16) int2    g_colw[EE];     // CSR slot: {src, weight bits}
__device__ int    g_rank[EE];                    // edge rank within its dst
__device__ int    g_deg[NN];
__device__ float  g_dinv[NN];
__device__ int    g_rowptr[NN + 1];
__device__ int    g_bsum[NB];
__device__ int    g_boff[NB];
__device__ __align__(16) float   g_aggx[NN * 10];   // A @ x
__device__ __align__(16) float   g_h1[NN * 64];     // fp32 h1 (feeds gemm64 V2 pass)
__device__ __align__(16) __half2 g_h1h[NN * 32];    // fp16 mirror of h1 (agg64 gather)
__device__ __align__(16) float   g_aggf[NN * 64];   // A @ h1
__device__ __align__(16) float   g_gl[NN * 2];      // h2 @ W3
__device__ __align__(16) float   g_rl[NN * 2];      // h2 @ V3 + b3

// ---------------- preprocessing ----------------
__global__ void k_zero_deg() {
    int i = blockIdx.x * blockDim.x + threadIdx.x;
    if (i < NN) g_deg[i] = 0;
}

// edge_index is int32 (JAX x64 disabled). Save the degree atomic's return
// value: it is this edge's rank within its dst (atomic-free fill later).
__global__ void k_convert(const int* __restrict__ ei) {
    int e = blockIdx.x * blockDim.x + threadIdx.x;
    if (e >= EE) return;
    int d = ei[EE + e];
    d = min(max(d, 0), NN - 1);
    g_rank[e] = atomicAdd(&g_deg[d], 1);
}

// scan stage 1: per-block degree sums
__global__ void k_s1() {
    __shared__ int sh[256];
    int t = threadIdx.x;
    int i = blockIdx.x * 256 + t;
    sh[t] = (i < NN) ? g_deg[i] : 0;
    __syncthreads();
#pragma unroll
    for (int off = 128; off; off >>= 1) {
        if (t < off) sh[t] += sh[t + off];
        __syncthreads();
    }
    if (t == 0) g_bsum[blockIdx.x] = sh[0];
}

// scan stage 2: single block scans NB block sums -> exclusive offsets
__global__ void k_s2() {
    __shared__ int sh[512];
    int t = threadIdx.x;
    int v = (t < NB) ? g_bsum[t] : 0;
    sh[t] = v;
    __syncthreads();
    for (int off = 1; off < 512; off <<= 1) {
        int u = (t >= off) ? sh[t - off] : 0;
        __syncthreads();
        sh[t] += u;
        __syncthreads();
    }
    if (t < NB) g_boff[t] = sh[t] - v;   // exclusive
    if (t == 0) g_rowptr[NN] = EE;
}

// scan stage 3: per-block scatter of rowptr/dinv
__global__ void k_s3() {
    __shared__ int sh[256];
    int t = threadIdx.x;
    int i = blockIdx.x * 256 + t;
    int d = (i < NN) ? g_deg[i] : 0;
    sh[t] = d;
    __syncthreads();
    for (int off = 1; off < 256; off <<= 1) {
        int u = (t >= off) ? sh[t - off] : 0;
        __syncthreads();
        sh[t] += u;
        __syncthreads();
    }
    if (i < NN) {
        int excl = g_boff[blockIdx.x] + sh[t] - d;
        g_rowptr[i] = excl;
        g_dinv[i] = (d > 0) ? rsqrtf((float)d) : 0.0f;
    }
}

// atomic-free CSR fill: pos = rowptr[dst] + precomputed rank
__global__ void k_fill(const int* __restrict__ ei) {
    int e = blockIdx.x * blockDim.x + threadIdx.x;
    if (e >= EE) return;
    int s = ei[e];
    int d = ei[EE + e];
    s = min(max(s, 0), NN - 1);
    d = min(max(d, 0), NN - 1);
    int pos = g_rowptr[d] + g_rank[e];
    float w = g_dinv[s] * g_dinv[d];
    g_colw[pos] = make_int2(s, __float_as_int(w));
}

// ---------------- agg layer 1: one warp per dst node (R4-proven) ----------------
__global__ void k_agg10(const float* __restrict__ x) {
    int wid = (blockIdx.x * blockDim.x + threadIdx.x) >> 5;
    int l = threadIdx.x & 31;
    if (wid >= NN) return;
    int s = g_rowptr[wid], e = g_rowptr[wid + 1];
    float acc = 0.0f;
    int p = s;
    for (; p + 3 < e; p += 4) {
        int2 c0 = g_colw[p], c1 = g_colw[p + 1], c2 = g_colw[p + 2], c3 = g_colw[p + 3];
        if (l < 10) {
            float v0 = __ldg(&x[c0.x * 10 + l]);
            float v1 = __ldg(&x[c1.x * 10 + l]);
            float v2 = __ldg(&x[c2.x * 10 + l]);
            float v3 = __ldg(&x[c3.x * 10 + l]);
            acc += __int_as_float(c0.y) * v0 + __int_as_float(c1.y) * v1
                 + __int_as_float(c2.y) * v2 + __int_as_float(c3.y) * v3;
        }
    }
    for (; p < e; p++) {
        int2 c0 = g_colw[p];
        if (l < 10) acc += __int_as_float(c0.y) * __ldg(&x[c0.x * 10 + l]);
    }
    if (l < 10) g_aggx[wid * 10 + l] = acc;
}

// ---------------- agg layer 2: fp16 gather, fp32 accumulate (R9-proven) ------------
__global__ void k_agg64() {
    int wid = (blockIdx.x * blockDim.x + threadIdx.x) >> 5;
    int l = threadIdx.x & 31;
    if (wid >= NN) return;
    int s = g_rowptr[wid], e = g_rowptr[wid + 1];
    float ax = 0.0f, ay = 0.0f;
    int p = s;
    for (; p + 3 < e; p += 4) {
        int2 c0 = g_colw[p], c1 = g_colw[p + 1], c2 = g_colw[p + 2], c3 = g_colw[p + 3];
        float2 h0 = __half22float2(__ldg(&g_h1h[c0.x * 32 + l]));
        float2 h1 = __half22float2(__ldg(&g_h1h[c1.x * 32 + l]));
        float2 h2 = __half22float2(__ldg(&g_h1h[c2.x * 32 + l]));
        float2 h3 = __half22float2(__ldg(&g_h1h[c3.x * 32 + l]));
        float w0 = __int_as_float(c0.y), w1 = __int_as_float(c1.y);
        float w2 = __int_as_float(c2.y), w3 = __int_as_float(c3.y);
        ax += w0 * h0.x + w1 * h1.x + w2 * h2.x + w3 * h3.x;
        ay += w0 * h0.y + w1 * h1.y + w2 * h2.y + w3 * h3.y;
    }
    for (; p < e; p++) {
        int2 c0 = g_colw[p];
        float2 h0 = __half22float2(__ldg(&g_h1h[c0.x * 32 + l]));
        float w0 = __int_as_float(c0.y);
        ax += w0 * h0.x;
        ay += w0 * h0.y;
    }
    ((float2*)g_aggf)[wid * 32 + l] = make_float2(ax, ay);
}

// ---------------- layer 1 GEMM: h1 = relu(aggx@W1 + x@V1 + b1) ----------------
// epilogue writes fp32 h1 AND the fp16 mirror for the aggregation gather
__global__ __launch_bounds__(256) void k_gemm10(const float* __restrict__ Xin,
                                                const float* __restrict__ W,
                                                const float* __restrict__ V,
                                                const float* __restrict__ b) {
    __shared__ float sDT[10][68];
    __shared__ float sM[10][68];
    const int t = threadIdx.x;
    const int tx = t & 15;
    const int ty = t >> 4;
    const int node0 = blockIdx.x << 6;

    float acc[4][4];
#pragma unroll
    for (int i = 0; i < 4; i++)
#pragma unroll
        for (int j = 0; j < 4; j++) acc[i][j] = 0.0f;

#pragma unroll
    for (int pass = 0; pass < 2; pass++) {
        const float* D = pass ? Xin : g_aggx;
        const float* M = pass ? V : W;
        if (pass) __syncthreads();
        for (int i = t; i < 640; i += 256) {
            int k = i >> 6, c = i & 63;
            sM[k][c] = M[k * 64 + c];
        }
        for (int i = t; i < 640; i += 256) {
            int r = i / 10, c = i % 10;
            int node = node0 + r;
            sDT[c][r] = (node < NN) ? D[node * 10 + c] : 0.0f;
        }
        __syncthreads();
#pragma unroll
        for (int k = 0; k < 10; k++) {
            float4 a = *(const float4*)&sDT[k][ty << 2];
            float4 w = *(const float4*)&sM[k][tx << 2];
            acc[0][0] += a.x * w.x; acc[0][1] += a.x * w.y; acc[0][2] += a.x * w.z; acc[0][3] += a.x * w.w;
            acc[1][0] += a.y * w.x; acc[1][1] += a.y * w.y; acc[1][2] += a.y * w.z; acc[1][3] += a.y * w.w;
            acc[2][0] += a.z * w.x; acc[2][1] += a.z * w.y; acc[2][2] += a.z * w.z; acc[2][3] += a.z * w.w;
            acc[3][0] += a.w * w.x; acc[3][1] += a.w * w.y; acc[3][2] += a.w * w.z; acc[3][3] += a.w * w.w;
        }
    }

    float b0 = b[(tx << 2) + 0], b1 = b[(tx << 2) + 1];
    float b2 = b[(tx << 2) + 2], b3v = b[(tx << 2) + 3];
#pragma unroll
    for (int ii = 0; ii < 4; ii++) {
        int node = node0 + (ty << 2) + ii;
        if (node < NN) {
            float4 o;
            o.x = fmaxf(acc[ii][0] + b0, 0.0f);
            o.y = fmaxf(acc[ii][1] + b1, 0.0f);
            o.z = fmaxf(acc[ii][2] + b2, 0.0f);
            o.w = fmaxf(acc[ii][3] + b3v, 0.0f);
            *(float4*)&g_h1[node * 64 + (tx << 2)] = o;
            g_h1h[node * 32 + (tx << 1)]     = __floats2half2_rn(o.x, o.y);
            g_h1h[node * 32 + (tx << 1) + 1] = __floats2half2_rn(o.z, o.w);
        }
    }
}

// ---------------- layer 2 GEMM (f32x2 FMA + XOR-swizzled staging) + layer-3 ----
// sDT swizzle: logical (k, r) stored at column r ^ (((k>>3)&7)<<2).
// Varies with k>>3 — decorrelated from 4k mod 32 — turning the 8-way
// transposed-store bank conflict into 2-way. Load side stays an aligned
// float4 (swizzle is a multiple of 4) and a 2-address warp broadcast.
__global__ __launch_bounds__(256) void k_gemm64_fused(const float* __restrict__ W2,
                                                      const float* __restrict__ V2,
                                                      const float* __restrict__ b2,
                                                      const float* __restrict__ W3,
                                                      const float* __restrict__ V3,
                                                      const float* __restrict__ b3) {
    __shared__ float sDT[64][68];
    __shared__ float sM[64][68];
    const int t = threadIdx.x;
    const int tx = t & 15;
    const int ty = t >> 4;
    const int node0 = blockIdx.x << 6;

    unsigned long long acc2[4][2];
#pragma unroll
    for (int i = 0; i < 4; i++) { acc2[i][0] = 0ull; acc2[i][1] = 0ull; }

#pragma unroll
    for (int pass = 0; pass < 2; pass++) {
        const float* D = pass ? g_h1 : g_aggf;
        const float* M = pass ? V2 : W2;
        if (pass) __syncthreads();
        for (int i4 = t; i4 < 1024; i4 += 256) {
            int k = i4 >> 4, c4 = (i4 & 15) << 2;
            float4 v = ((const float4*)M)[i4];
            *(float4*)&sM[k][c4] = v;
        }
        for (int i4 = t; i4 < 1024; i4 += 256) {
            int r = i4 >> 4, c4 = (i4 & 15) << 2;
            int node = node0 + r;
            float4 v = (node < NN) ? *(const float4*)&D[node * 64 + c4]
                                   : make_float4(0.f, 0.f, 0.f, 0.f);
            // swizzled transpose store: column r ^ (((k>>3)&7)<<2) per k-row
            sDT[c4 + 0][r ^ ((((c4 + 0) >> 3) & 7) << 2)] = v.x;
            sDT[c4 + 1][r ^ ((((c4 + 1) >> 3) & 7) << 2)] = v.y;
            sDT[c4 + 2][r ^ ((((c4 + 2) >> 3) & 7) << 2)] = v.z;
            sDT[c4 + 3][r ^ ((((c4 + 3) >> 3) & 7) << 2)] = v.w;
        }
        __syncthreads();
#pragma unroll
        for (int k = 0; k < 64; k++) {
            int swz = ((k >> 3) & 7) << 2;
            float4 a = *(const float4*)&sDT[k][(ty << 2) ^ swz];
            ulonglong2 wp = *(const ulonglong2*)&sM[k][tx << 2];
            unsigned long long d0 = dup2(a.x), d1 = dup2(a.y);
            unsigned long long d2 = dup2(a.z), d3 = dup2(a.w);
            ffma2(acc2[0][0], d0, wp.x); ffma2(acc2[0][1], d0, wp.y);
            ffma2(acc2[1][0], d1, wp.x); ffma2(acc2[1][1], d1, wp.y);
            ffma2(acc2[2][0], d2, wp.x); ffma2(acc2[2][1], d2, wp.y);
            ffma2(acc2[3][0], d3, wp.x); ffma2(acc2[3][1], d3, wp.y);
        }
    }

    float acc[4][4];
#pragma unroll
    for (int i = 0; i < 4; i++) {
        float2 p0 = unpack2(acc2[i][0]);
        float2 p1 = unpack2(acc2[i][1]);
        acc[i][0] = p0.x; acc[i][1] = p0.y; acc[i][2] = p1.x; acc[i][3] = p1.y;
    }

    // epilogue: relu + layer-3 transform, reduced across the 16 tx-lanes
    float bb[4], w3a[4], w3b[4], v3a[4], v3b[4];
#pragma unroll
    for (int j = 0; j < 4; j++) {
        int f = (tx << 2) + j;
        bb[j] = b2[f];
        w3a[j] = W3[f * 2];
        w3b[j] = W3[f * 2 + 1];
        v3a[j] = V3[f * 2];
        v3b[j] = V3[f * 2 + 1];
    }
    float b3_0 = b3[0], b3_1 = b3[1];

#pragma unroll
    for (int ii = 0; ii < 4; ii++) {
        float g0 = 0.f, g1 = 0.f, r0 = 0.f, r1 = 0.f;
#pragma unroll
        for (int j = 0; j < 4; j++) {
            float hv = fmaxf(acc[ii][j] + bb[j], 0.0f);
            g0 += hv * w3a[j];
            g1 += hv * w3b[j];
            r0 += hv * v3a[j];
            r1 += hv * v3b[j];
        }
#pragma unroll
        for (int off = 1; off < 16; off <<= 1) {
            g0 += __shfl_xor_sync(0xffffffffu, g0, off);
            g1 += __shfl_xor_sync(0xffffffffu, g1, off);
            r0 += __shfl_xor_sync(0xffffffffu, r0, off);
            r1 += __shfl_xor_sync(0xffffffffu, r1, off);
        }
        int node = node0 + (ty << 2) + ii;
        if (tx == 0 && node < NN) {
            g_gl[node * 2] = g0;
            g_gl[node * 2 + 1] = g1;
            g_rl[node * 2] = r0 + b3_0;
            g_rl[node * 2 + 1] = r1 + b3_1;
        }
    }
}

// ---------------- final: out = log_softmax(A@g + r), 8 lanes per node ----------------
__global__ void k_final(float* __restrict__ out) {
    int gtid = blockIdx.x * blockDim.x + threadIdx.x;
    int node = gtid >> 3;
    int sl = threadIdx.x & 7;
    if (node >= NN) return;
    int s = g_rowptr[node], e = g_rowptr[node + 1];
    const float2* GL = (const float2*)g_gl;
    float a0 = 0.f, a1 = 0.f;
    for (int p = s + sl; p < e; p += 8) {
        int2 cw = g_colw[p];
        float w = __int_as_float(cw.y);
        float2 gv = __ldg(&GL[cw.x]);
        a0 += w * gv.x;
        a1 += w * gv.y;
    }
#pragma unroll
    for (int off = 4; off; off >>= 1) {
        a0 += __shfl_xor_sync(0xffffffffu, a0, off);
        a1 += __shfl_xor_sync(0xffffffffu, a1, off);
    }
    if (sl == 0) {
        float z0 = a0 + g_rl[node * 2];
        float z1 = a1 + g_rl[node * 2 + 1];
        float m = fmaxf(z0, z1);
        float lse = m + logf(expf(z0 - m) + expf(z1 - m));
        out[node * 2] = z0 - lse;
        out[node * 2 + 1] = z1 - lse;
    }
}

// ---------------- launch ----------------
extern "C" void kernel_launch(void* const* d_in, const int* in_sizes, int n_in,
                              void* d_out, int out_size) {
    const float* x = (const float*)d_in[0];
    const int* ei = (const int*)d_in[1];     // int32 (JAX x64 disabled)
    const float* W1 = (const float*)d_in[2];
    const float* V1 = (const float*)d_in[3];
    const float* b1 = (const float*)d_in[4];
    const float* W2 = (const float*)d_in[5];
    const float* V2 = (const float*)d_in[6];
    const float* b2 = (const float*)d_in[7];
    const float* W3 = (const float*)d_in[8];
    const float* V3 = (const float*)d_in[9];
    const float* b3 = (const float*)d_in[10];
    float* out = (float*)d_out;

    k_zero_deg<<<NB, 256>>>();
    k_convert<<<(EE + 255) / 256, 256>>>(ei);
    k_s1<<<NB, 256>>>();
    k_s2<<<1, 512>>>();
    k_s3<<<NB, 256>>>();
    k_fill<<<(EE + 255) / 256, 256>>>(ei);

    // layer 1: h1 = relu((A@x)@W1 + x@V1 + b1)
    k_agg10<<<(NN * 32 + 255) / 256, 256>>>(x);
    k_gemm10<<<(NN + 63) / 64, 256>>>(x, W1, V1, b1);

    // layer 2 (f32x2 FMA, swizzled staging) + layer-3 transform
    k_agg64<<<(NN * 32 + 255) / 256, 256>>>();
    k_gemm64_fused<<<(NN + 63) / 64, 256>>>(W2, V2, b2, W3, V3, b3);

    // final aggregation + log_softmax
    k_final<<<(NN * 8 + 255) / 256, 256>>>(out);
}

// round 14
// speedup vs baseline: 1.1001x; 1.1001x over previous
#include <cuda_runtime.h>
#include <cuda_fp16.h>

#define NN 100000
#define EE 1600000
#define NB ((NN + 255) / 256)   // 391 blocks of 256

// ---------------- scratch (static device globals; no runtime alloc) ----------------
__device__ __align__(16) int2    g_colw[EE];     // CSR slot: {src, weight bits}
__device__ int    g_rank[EE];                    // edge rank within its dst
__device__ int    g_deg[NN];
__device__ float  g_dinv[NN];
__device__ int    g_rowptr[NN + 1];
__device__ int    g_bsum[NB];
__device__ int    g_boff[NB];
__device__ __align__(16) float   g_aggx[NN * 10];   // A @ x
__device__ __align__(16) __half2 g_h1h[NN * 32];    // fp16 h1 (sole h1 representation)
__device__ __align__(16) float   g_gl[NN * 2];      // h2 @ W3
__device__ __align__(16) float   g_rl[NN * 2];      // h2 @ V3 + b3

// ---------------- preprocessing ----------------
__global__ void k_zero_deg() {
    int i = blockIdx.x * blockDim.x + threadIdx.x;
    if (i < NN) g_deg[i] = 0;
}

// edge_index is int32 (JAX x64 disabled). Save the degree atomic's return
// value: it is this edge's rank within its dst (atomic-free fill later).
__global__ void k_convert(const int* __restrict__ ei) {
    int e = blockIdx.x * blockDim.x + threadIdx.x;
    if (e >= EE) return;
    int d = ei[EE + e];
    d = min(max(d, 0), NN - 1);
    g_rank[e] = atomicAdd(&g_deg[d], 1);
}

// scan stage 1: per-block degree sums
__global__ void k_s1() {
    __shared__ int sh[256];
    int t = threadIdx.x;
    int i = blockIdx.x * 256 + t;
    sh[t] = (i < NN) ? g_deg[i] : 0;
    __syncthreads();
#pragma unroll
    for (int off = 128; off; off >>= 1) {
        if (t < off) sh[t] += sh[t + off];
        __syncthreads();
    }
    if (t == 0) g_bsum[blockIdx.x] = sh[0];
}

// scan stage 2: single block scans NB block sums -> exclusive offsets
__global__ void k_s2() {
    __shared__ int sh[512];
    int t = threadIdx.x;
    int v = (t < NB) ? g_bsum[t] : 0;
    sh[t] = v;
    __syncthreads();
    for (int off = 1; off < 512; off <<= 1) {
        int u = (t >= off) ? sh[t - off] : 0;
        __syncthreads();
        sh[t] += u;
        __syncthreads();
    }
    if (t < NB) g_boff[t] = sh[t] - v;   // exclusive
    if (t == 0) g_rowptr[NN] = EE;
}

// scan stage 3: per-block scatter of rowptr/dinv
__global__ void k_s3() {
    __shared__ int sh[256];
    int t = threadIdx.x;
    int i = blockIdx.x * 256 + t;
    int d = (i < NN) ? g_deg[i] : 0;
    sh[t] = d;
    __syncthreads();
    for (int off = 1; off < 256; off <<= 1) {
        int u = (t >= off) ? sh[t - off] : 0;
        __syncthreads();
        sh[t] += u;
        __syncthreads();
    }
    if (i < NN) {
        int excl = g_boff[blockIdx.x] + sh[t] - d;
        g_rowptr[i] = excl;
        g_dinv[i] = (d > 0) ? rsqrtf((float)d) : 0.0f;
    }
}

// atomic-free CSR fill: pos = rowptr[dst] + precomputed rank
__global__ void k_fill(const int* __restrict__ ei) {
    int e = blockIdx.x * blockDim.x + threadIdx.x;
    if (e >= EE) return;
    int s = ei[e];
    int d = ei[EE + e];
    s = min(max(s, 0), NN - 1);
    d = min(max(d, 0), NN - 1);
    int pos = g_rowptr[d] + g_rank[e];
    float w = g_dinv[s] * g_dinv[d];
    g_colw[pos] = make_int2(s, __float_as_int(w));
}

// ---------------- agg layer 1: one warp per dst node (R4-proven) ----------------
__global__ void k_agg10(const float* __restrict__ x) {
    int wid = (blockIdx.x * blockDim.x + threadIdx.x) >> 5;
    int l = threadIdx.x & 31;
    if (wid >= NN) return;
    int s = g_rowptr[wid], e = g_rowptr[wid + 1];
    float acc = 0.0f;
    int p = s;
    for (; p + 3 < e; p += 4) {
        int2 c0 = g_colw[p], c1 = g_colw[p + 1], c2 = g_colw[p + 2], c3 = g_colw[p + 3];
        if (l < 10) {
            float v0 = __ldg(&x[c0.x * 10 + l]);
            float v1 = __ldg(&x[c1.x * 10 + l]);
            float v2 = __ldg(&x[c2.x * 10 + l]);
            float v3 = __ldg(&x[c3.x * 10 + l]);
            acc += __int_as_float(c0.y) * v0 + __int_as_float(c1.y) * v1
                 + __int_as_float(c2.y) * v2 + __int_as_float(c3.y) * v3;
        }
    }
    for (; p < e; p++) {
        int2 c0 = g_colw[p];
        if (l < 10) acc += __int_as_float(c0.y) * __ldg(&x[c0.x * 10 + l]);
    }
    if (l < 10) g_aggx[wid * 10 + l] = acc;
}

// ---------------- layer 1 GEMM: h1 = relu(aggx@W1 + x@V1 + b1), fp16 out ----------
__global__ __launch_bounds__(256) void k_gemm10(const float* __restrict__ Xin,
                                                const float* __restrict__ W,
                                                const float* __restrict__ V,
                                                const float* __restrict__ b) {
    __shared__ float sDT[10][68];
    __shared__ float sM[10][68];
    const int t = threadIdx.x;
    const int tx = t & 15;
    const int ty = t >> 4;
    const int node0 = blockIdx.x << 6;

    float acc[4][4];
#pragma unroll
    for (int i = 0; i < 4; i++)
#pragma unroll
        for (int j = 0; j < 4; j++) acc[i][j] = 0.0f;

#pragma unroll
    for (int pass = 0; pass < 2; pass++) {
        const float* D = pass ? Xin : g_aggx;
        const float* M = pass ? V : W;
        if (pass) __syncthreads();
        for (int i = t; i < 640; i += 256) {
            int k = i >> 6, c = i & 63;
            sM[k][c] = M[k * 64 + c];
        }
        for (int i = t; i < 640; i += 256) {
            int r = i / 10, c = i % 10;
            int node = node0 + r;
            sDT[c][r] = (node < NN) ? D[node * 10 + c] : 0.0f;
        }
        __syncthreads();
#pragma unroll
        for (int k = 0; k < 10; k++) {
            float4 a = *(const float4*)&sDT[k][ty << 2];
            float4 w = *(const float4*)&sM[k][tx << 2];
            acc[0][0] += a.x * w.x; acc[0][1] += a.x * w.y; acc[0][2] += a.x * w.z; acc[0][3] += a.x * w.w;
            acc[1][0] += a.y * w.x; acc[1][1] += a.y * w.y; acc[1][2] += a.y * w.z; acc[1][3] += a.y * w.w;
            acc[2][0] += a.z * w.x; acc[2][1] += a.z * w.y; acc[2][2] += a.z * w.z; acc[2][3] += a.z * w.w;
            acc[3][0] += a.w * w.x; acc[3][1] += a.w * w.y; acc[3][2] += a.w * w.z; acc[3][3] += a.w * w.w;
        }
    }

    float b0 = b[(tx << 2) + 0], b1 = b[(tx << 2) + 1];
    float b2 = b[(tx << 2) + 2], b3v = b[(tx << 2) + 3];
#pragma unroll
    for (int ii = 0; ii < 4; ii++) {
        int node = node0 + (ty << 2) + ii;
        if (node < NN) {
            float ox = fmaxf(acc[ii][0] + b0, 0.0f);
            float oy = fmaxf(acc[ii][1] + b1, 0.0f);
            float oz = fmaxf(acc[ii][2] + b2, 0.0f);
            float ow = fmaxf(acc[ii][3] + b3v, 0.0f);
            g_h1h[node * 32 + (tx << 1)]     = __floats2half2_rn(ox, oy);
            g_h1h[node * 32 + (tx << 1) + 1] = __floats2half2_rn(oz, ow);
        }
    }
}

// ---------------- FUSED layer 2: gather + dual GEMM + layer-3 transform ----------
// Phase 1: gather (A@h1) for this block's 64 nodes straight into the GEMM smem
// tile (swizzled transpose, R13-validated formula). Phase 2: the proven R9
// mainloop (pass 0 on gathered tile + W2; pass 1 on h1h + V2), then the
// relu -> {W3,V3} -> shfl epilogue. Blocks desynchronize -> gather (memory)
// and GEMM (FMA) phases overlap across the chip.
__global__ __launch_bounds__(256) void k_layer2(const float* __restrict__ W2,
                                                const float* __restrict__ V2,
                                                const float* __restrict__ b2,
                                                const float* __restrict__ W3,
                                                const float* __restrict__ V3,
                                                const float* __restrict__ b3) {
    __shared__ float sDT[64][68];
    __shared__ float sM[64][68];
    const int t = threadIdx.x;
    const int lane = t & 31;
    const int wrp = t >> 5;          // 0..7
    const int tx = t & 15;
    const int ty = t >> 4;
    const int node0 = blockIdx.x << 6;

    // stage sM = W2 (independent of the gather)
    for (int i4 = t; i4 < 1024; i4 += 256) {
        int k = i4 >> 4, c4 = (i4 & 15) << 2;
        float4 v = ((const float4*)W2)[i4];
        *(float4*)&sM[k][c4] = v;
    }

    // phase 1: warp wrp gathers nodes node0 + wrp*8 .. +7; lane covers feats 2l,2l+1
#pragma unroll 1
    for (int n = 0; n < 8; n++) {
        int r = (wrp << 3) + n;
        int node = node0 + r;
        float ax = 0.0f, ay = 0.0f;
        if (node < NN) {
            int s = g_rowptr[node], e = g_rowptr[node + 1];
            int p = s;
            for (; p + 3 < e; p += 4) {
                int2 c0 = g_colw[p], c1 = g_colw[p + 1], c2 = g_colw[p + 2], c3 = g_colw[p + 3];
                float2 h0 = __half22float2(__ldg(&g_h1h[c0.x * 32 + lane]));
                float2 h1 = __half22float2(__ldg(&g_h1h[c1.x * 32 + lane]));
                float2 h2 = __half22float2(__ldg(&g_h1h[c2.x * 32 + lane]));
                float2 h3 = __half22float2(__ldg(&g_h1h[c3.x * 32 + lane]));
                float w0 = __int_as_float(c0.y), w1 = __int_as_float(c1.y);
                float w2 = __int_as_float(c2.y), w3 = __int_as_float(c3.y);
                ax += w0 * h0.x + w1 * h1.x + w2 * h2.x + w3 * h3.x;
                ay += w0 * h0.y + w1 * h1.y + w2 * h2.y + w3 * h3.y;
            }
            for (; p < e; p++) {
                int2 c0 = g_colw[p];
                float2 h0 = __half22float2(__ldg(&g_h1h[c0.x * 32 + lane]));
                float w0 = __int_as_float(c0.y);
                ax += w0 * h0.x;
                ay += w0 * h0.y;
            }
        }
        int k0 = 2 * lane, k1 = 2 * lane + 1;
        sDT[k0][r ^ (((k0 >> 3) & 7) << 2)] = ax;
        sDT[k1][r ^ (((k1 >> 3) & 7) << 2)] = ay;
    }
    __syncthreads();

    float acc[4][4];
#pragma unroll
    for (int i = 0; i < 4; i++)
#pragma unroll
        for (int j = 0; j < 4; j++) acc[i][j] = 0.0f;

    // mainloop pass 0: gathered tile @ W2
#pragma unroll
    for (int k = 0; k < 64; k++) {
        int swz = ((k >> 3) & 7) << 2;
        float4 a = *(const float4*)&sDT[k][(ty << 2) ^ swz];
        float4 w = *(const float4*)&sM[k][tx << 2];
        acc[0][0] += a.x * w.x; acc[0][1] += a.x * w.y; acc[0][2] += a.x * w.z; acc[0][3] += a.x * w.w;
        acc[1][0] += a.y * w.x; acc[1][1] += a.y * w.y; acc[1][2] += a.y * w.z; acc[1][3] += a.y * w.w;
        acc[2][0] += a.z * w.x; acc[2][1] += a.z * w.y; acc[2][2] += a.z * w.z; acc[2][3] += a.z * w.w;
        acc[3][0] += a.w * w.x; acc[3][1] += a.w * w.y; acc[3][2] += a.w * w.z; acc[3][3] += a.w * w.w;
    }
    __syncthreads();

    // restage: sDT <- h1h (dequant, swizzled transpose), sM <- V2
    for (int i4 = t; i4 < 1024; i4 += 256) {
        int k = i4 >> 4, c4 = (i4 & 15) << 2;
        float4 v = ((const float4*)V2)[i4];
        *(float4*)&sM[k][c4] = v;
    }
    for (int i = t; i < 512; i += 256) {
        int r = i >> 3, c = i & 7;           // node r, halves 8c..8c+7
        int node = node0 + r;
        float f[8];
        if (node < NN) {
            int4 v = ((const int4*)g_h1h)[node * 8 + c];
            __half2* hp = (__half2*)&v;
#pragma unroll
            for (int j = 0; j < 4; j++) {
                float2 p2 = __half22float2(hp[j]);
                f[2 * j] = p2.x;
                f[2 * j + 1] = p2.y;
            }
        } else {
#pragma unroll
            for (int j = 0; j < 8; j++) f[j] = 0.0f;
        }
        int swz = c << 2;                    // ((k>>3)&7)<<2 with k = 8c+j
#pragma unroll
        for (int j = 0; j < 8; j++)
            sDT[c * 8 + j][r ^ swz] = f[j];
    }
    __syncthreads();

    // mainloop pass 1: h1 tile @ V2
#pragma unroll
    for (int k = 0; k < 64; k++) {
        int swz = ((k >> 3) & 7) << 2;
        float4 a = *(const float4*)&sDT[k][(ty << 2) ^ swz];
        float4 w = *(const float4*)&sM[k][tx << 2];
        acc[0][0] += a.x * w.x; acc[0][1] += a.x * w.y; acc[0][2] += a.x * w.z; acc[0][3] += a.x * w.w;
        acc[1][0] += a.y * w.x; acc[1][1] += a.y * w.y; acc[1][2] += a.y * w.z; acc[1][3] += a.y * w.w;
        acc[2][0] += a.z * w.x; acc[2][1] += a.z * w.y; acc[2][2] += a.z * w.z; acc[2][3] += a.z * w.w;
        acc[3][0] += a.w * w.x; acc[3][1] += a.w * w.y; acc[3][2] += a.w * w.z; acc[3][3] += a.w * w.w;
    }

    // epilogue: relu + layer-3 transform, reduced across the 16 tx-lanes
    float bb[4], w3a[4], w3b[4], v3a[4], v3b[4];
#pragma unroll
    for (int j = 0; j < 4; j++) {
        int f = (tx << 2) + j;
        bb[j] = b2[f];
        w3a[j] = W3[f * 2];
        w3b[j] = W3[f * 2 + 1];
        v3a[j] = V3[f * 2];
        v3b[j] = V3[f * 2 + 1];
    }
    float b3_0 = b3[0], b3_1 = b3[1];

#pragma unroll
    for (int ii = 0; ii < 4; ii++) {
        float g0 = 0.f, g1 = 0.f, r0 = 0.f, r1 = 0.f;
#pragma unroll
        for (int j = 0; j < 4; j++) {
            float hv = fmaxf(acc[ii][j] + bb[j], 0.0f);
            g0 += hv * w3a[j];
            g1 += hv * w3b[j];
            r0 += hv * v3a[j];
            r1 += hv * v3b[j];
        }
#pragma unroll
        for (int off = 1; off < 16; off <<= 1) {
            g0 += __shfl_xor_sync(0xffffffffu, g0, off);
            g1 += __shfl_xor_sync(0xffffffffu, g1, off);
            r0 += __shfl_xor_sync(0xffffffffu, r0, off);
            r1 += __shfl_xor_sync(0xffffffffu, r1, off);
        }
        int node = node0 + (ty << 2) + ii;
        if (tx == 0 && node < NN) {
            g_gl[node * 2] = g0;
            g_gl[node * 2 + 1] = g1;
            g_rl[node * 2] = r0 + b3_0;
            g_rl[node * 2 + 1] = r1 + b3_1;
        }
    }
}

// ---------------- final: out = log_softmax(A@g + r), 8 lanes per node ----------------
__global__ void k_final(float* __restrict__ out) {
    int gtid = blockIdx.x * blockDim.x + threadIdx.x;
    int node = gtid >> 3;
    int sl = threadIdx.x & 7;
    if (node >= NN) return;
    int s = g_rowptr[node], e = g_rowptr[node + 1];
    const float2* GL = (const float2*)g_gl;
    float a0 = 0.f, a1 = 0.f;
    for (int p = s + sl; p < e; p += 8) {
        int2 cw = g_colw[p];
        float w = __int_as_float(cw.y);
        float2 gv = __ldg(&GL[cw.x]);
        a0 += w * gv.x;
        a1 += w * gv.y;
    }
#pragma unroll
    for (int off = 4; off; off >>= 1) {
        a0 += __shfl_xor_sync(0xffffffffu, a0, off);
        a1 += __shfl_xor_sync(0xffffffffu, a1, off);
    }
    if (sl == 0) {
        float z0 = a0 + g_rl[node * 2];
        float z1 = a1 + g_rl[node * 2 + 1];
        float m = fmaxf(z0, z1);
        float lse = m + logf(expf(z0 - m) + expf(z1 - m));
        out[node * 2] = z0 - lse;
        out[node * 2 + 1] = z1 - lse;
    }
}

// ---------------- launch ----------------
extern "C" void kernel_launch(void* const* d_in, const int* in_sizes, int n_in,
                              void* d_out, int out_size) {
    const float* x = (const float*)d_in[0];
    const int* ei = (const int*)d_in[1];     // int32 (JAX x64 disabled)
    const float* W1 = (const float*)d_in[2];
    const float* V1 = (const float*)d_in[3];
    const float* b1 = (const float*)d_in[4];
    const float* W2 = (const float*)d_in[5];
    const float* V2 = (const float*)d_in[6];
    const float* b2 = (const float*)d_in[7];
    const float* W3 = (const float*)d_in[8];
    const float* V3 = (const float*)d_in[9];
    const float* b3 = (const float*)d_in[10];
    float* out = (float*)d_out;

    k_zero_deg<<<NB, 256>>>();
    k_convert<<<(EE + 255) / 256, 256>>>(ei);
    k_s1<<<NB, 256>>>();
    k_s2<<<1, 512>>>();
    k_s3<<<NB, 256>>>();
    k_fill<<<(EE + 255) / 256, 256>>>(ei);

    // layer 1: h1 = relu((A@x)@W1 + x@V1 + b1)  (fp16 output)
    k_agg10<<<(NN * 32 + 255) / 256, 256>>>(x);
    k_gemm10<<<(NN + 63) / 64, 256>>>(x, W1, V1, b1);

    // fused layer 2 + layer-3 transform (gather + GEMM in one kernel)
    k_layer2<<<(NN + 63) / 64, 256>>>(W2, V2, b2, W3, V3, b3);

    // final aggregation + log_softmax
    k_final<<<(NN * 8 + 255) / 256, 256>>>(out);
}